// round 1
// baseline (speedup 1.0000x reference)
#include <cuda_runtime.h>

#define BATCH 4
#define CH    64
#define HH    512
#define WWID  512
#define OH    256
#define OW    256
#define REDC  16
#define NWGT  36   // G * K * K = 4 * 9

// Scratch (allocation-free rule: __device__ globals)
__device__ float g_y[(size_t)BATCH * CH * HH * WWID];     // conv3x3 output (268 MB)
__device__ float g_wgt[(size_t)BATCH * NWGT * OH * OW];   // involution weights (37.7 MB)

// ---------------------------------------------------------------------------
// Kernel 1: y = relu(conv3x3(x, w1) + b1), pad=1, stride=1
// Block: 256 threads = 16(tx: 4px each) x 4(ty: rows) x 4(tz: 8 oc each)
// Block tile: 64w x 4h pixels, 32 output channels. Grid.z = batch*2 oc-halves.
// ---------------------------------------------------------------------------
__global__ __launch_bounds__(256) void conv3x3_relu_kernel(
    const float* __restrict__ x, const float* __restrict__ w1,
    const float* __restrict__ b1)
{
    const int ICC = 16;
    __shared__ float s_in[ICC][6][68];   // 66 cols used, padded
    __shared__ float s_w[32][ICC][9];

    int tid = threadIdx.x;
    int tx = tid & 15;
    int ty = (tid >> 4) & 3;
    int tz = tid >> 6;
    int wbase = blockIdx.x * 64;
    int hbase = blockIdx.y * 4;
    int b    = blockIdx.z >> 1;
    int ocb  = (blockIdx.z & 1) * 32;

    const float* xb = x + (size_t)b * CH * HH * WWID;

    float acc[8][4];
#pragma unroll
    for (int o = 0; o < 8; o++)
#pragma unroll
        for (int p = 0; p < 4; p++) acc[o][p] = 0.f;

    for (int ic0 = 0; ic0 < CH; ic0 += ICC) {
        __syncthreads();
        // stage input tile: ICC x 6 x 66 (with halo, zero-padded at borders)
        for (int i = tid; i < ICC * 6 * 66; i += 256) {
            int c  = i % 66;
            int r  = (i / 66) % 6;
            int ic = i / (66 * 6);
            int hh = hbase - 1 + r;
            int ww = wbase - 1 + c;
            float v = 0.f;
            if ((unsigned)hh < HH && (unsigned)ww < WWID)
                v = xb[(size_t)(ic0 + ic) * HH * WWID + (size_t)hh * WWID + ww];
            s_in[ic][r][c] = v;
        }
        // stage weights: 32 oc x ICC x 9
        for (int i = tid; i < 32 * ICC * 9; i += 256) {
            int k  = i % 9;
            int ic = (i / 9) % ICC;
            int oc = i / (9 * ICC);
            s_w[oc][ic][k] = w1[((size_t)(ocb + oc) * CH + (ic0 + ic)) * 9 + k];
        }
        __syncthreads();

#pragma unroll 1
        for (int ic = 0; ic < ICC; ic++) {
#pragma unroll
            for (int kh = 0; kh < 3; kh++) {
                float4 v4 = *reinterpret_cast<const float4*>(&s_in[ic][ty + kh][tx * 4]);
                float in[6];
                in[0] = v4.x; in[1] = v4.y; in[2] = v4.z; in[3] = v4.w;
                in[4] = s_in[ic][ty + kh][tx * 4 + 4];
                in[5] = s_in[ic][ty + kh][tx * 4 + 5];
#pragma unroll
                for (int kw = 0; kw < 3; kw++) {
#pragma unroll
                    for (int o = 0; o < 8; o++) {
                        float wv = s_w[tz * 8 + o][ic][kh * 3 + kw];  // warp-uniform (broadcast)
#pragma unroll
                        for (int p = 0; p < 4; p++)
                            acc[o][p] = fmaf(in[kw + p], wv, acc[o][p]);
                    }
                }
            }
        }
    }

    int h  = hbase + ty;
    int wc = wbase + tx * 4;
#pragma unroll
    for (int o = 0; o < 8; o++) {
        int oc = ocb + tz * 8 + o;
        float bias = b1[oc];
        float4 r;
        r.x = fmaxf(acc[o][0] + bias, 0.f);
        r.y = fmaxf(acc[o][1] + bias, 0.f);
        r.z = fmaxf(acc[o][2] + bias, 0.f);
        r.w = fmaxf(acc[o][3] + bias, 0.f);
        *reinterpret_cast<float4*>(
            &g_y[((size_t)b * CH + oc) * HH * WWID + (size_t)h * WWID + wc]) = r;
    }
}

// ---------------------------------------------------------------------------
// Kernel 2: kernel-generating branch, fully fused per output pixel:
//   pooled[64] (2x2 avg of y) -> t[16] = relu(BN(wr.pooled + br)) -> wgt[36]
// Thread per (b,h,w) pixel at 256x256. One block = one output row.
// ---------------------------------------------------------------------------
__global__ __launch_bounds__(256) void genw_kernel(
    const float* __restrict__ wr, const float* __restrict__ br,
    const float* __restrict__ gamma, const float* __restrict__ beta,
    const float* __restrict__ mean,  const float* __restrict__ var,
    const float* __restrict__ ws,    const float* __restrict__ bs)
{
    __shared__ float s_wr[64][16];   // [c][r]
    __shared__ float s_ws[36][16];
    __shared__ float s_scale[16], s_shift[16], s_br[16], s_bs[36];

    int tid = threadIdx.x;
    for (int i = tid; i < 1024; i += 256) {
        int r = i % 16, c = i / 16;
        s_wr[c][r] = wr[r * 64 + c];
    }
    for (int i = tid; i < 576; i += 256) {
        int r = i % 16, o = i / 16;
        s_ws[o][r] = ws[o * 16 + r];
    }
    if (tid < 16) {
        float sc = gamma[tid] * rsqrtf(var[tid] + 1e-5f);
        s_scale[tid] = sc;
        s_shift[tid] = beta[tid] - mean[tid] * sc;
        s_br[tid] = br[tid];
    }
    if (tid < 36) s_bs[tid] = bs[tid];
    __syncthreads();

    int idx = blockIdx.x * 256 + tid;
    int b = idx >> 16;
    int p = idx & 0xFFFF;
    int h = p >> 8;
    int w = p & 255;

    const float* yb = g_y + (size_t)b * CH * HH * WWID + (size_t)(2 * h) * WWID + 2 * w;

    float t[16];
#pragma unroll
    for (int r = 0; r < REDC; r++) t[r] = s_br[r];

    for (int c = 0; c < CH; c++) {
        const float* pp = yb + (size_t)c * HH * WWID;
        float pool = (pp[0] + pp[1] + pp[WWID] + pp[WWID + 1]) * 0.25f;
#pragma unroll
        for (int r = 0; r < REDC; r++) t[r] = fmaf(pool, s_wr[c][r], t[r]);
    }
#pragma unroll
    for (int r = 0; r < REDC; r++)
        t[r] = fmaxf(fmaf(t[r], s_scale[r], s_shift[r]), 0.f);

#pragma unroll 4
    for (int o = 0; o < NWGT; o++) {
        float a = s_bs[o];
#pragma unroll
        for (int r = 0; r < REDC; r++) a = fmaf(t[r], s_ws[o][r], a);
        g_wgt[(((size_t)b * NWGT + o) << 16) + p] = a;
    }
}

// ---------------------------------------------------------------------------
// Kernel 3: involution (stride 2, K=3, pad 1) + relu + 1x1(w3) + relu.
// Thread per output pixel; z[64] kept in registers (all z-loops fully unrolled).
// ---------------------------------------------------------------------------
__global__ __launch_bounds__(256) void inv_out_kernel(
    const float* __restrict__ w3, const float* __restrict__ b3,
    float* __restrict__ out)
{
    __shared__ float s_w3[64][64];
    __shared__ float s_b3[64];
    int tid = threadIdx.x;
    for (int i = tid; i < 4096; i += 256) s_w3[i >> 6][i & 63] = w3[i];
    if (tid < 64) s_b3[tid] = b3[tid];
    __syncthreads();

    int idx = blockIdx.x * 256 + tid;
    int b = idx >> 16;
    int p = idx & 0xFFFF;
    int h = p >> 8;
    int w = p & 255;

    const float* yb = g_y + (size_t)b * CH * HH * WWID;

    float z[64];
#pragma unroll
    for (int g = 0; g < 4; g++) {
        float wg[9];
#pragma unroll
        for (int k = 0; k < 9; k++)
            wg[k] = g_wgt[(((size_t)b * NWGT + g * 9 + k) << 16) + p];
#pragma unroll
        for (int cc = 0; cc < 16; cc++) {
            int c = g * 16 + cc;
            const float* yc = yb + (size_t)c * HH * WWID;
            float a = 0.f;
#pragma unroll
            for (int kh = 0; kh < 3; kh++) {
                int row = 2 * h - 1 + kh;
#pragma unroll
                for (int kw = 0; kw < 3; kw++) {
                    int col = 2 * w - 1 + kw;
                    float v = 0.f;
                    if ((unsigned)row < HH && (unsigned)col < WWID)
                        v = yc[(size_t)row * WWID + col];
                    a = fmaf(wg[kh * 3 + kw], v, a);
                }
            }
            z[c] = fmaxf(a, 0.f);
        }
    }

#pragma unroll 2
    for (int oc = 0; oc < CH; oc++) {
        float a = s_b3[oc];
#pragma unroll
        for (int c = 0; c < CH; c++) a = fmaf(z[c], s_w3[oc][c], a);  // broadcast LDS
        out[(((size_t)b * CH + oc) << 16) + p] = fmaxf(a, 0.f);
    }
}

// ---------------------------------------------------------------------------
extern "C" void kernel_launch(void* const* d_in, const int* in_sizes, int n_in,
                              void* d_out, int out_size)
{
    const float* x     = (const float*)d_in[0];
    const float* w1    = (const float*)d_in[1];
    const float* b1    = (const float*)d_in[2];
    const float* wr    = (const float*)d_in[3];
    const float* br    = (const float*)d_in[4];
    const float* gamma = (const float*)d_in[5];
    const float* beta  = (const float*)d_in[6];
    const float* mean  = (const float*)d_in[7];
    const float* var   = (const float*)d_in[8];
    const float* ws    = (const float*)d_in[9];
    const float* bs    = (const float*)d_in[10];
    const float* w3    = (const float*)d_in[11];
    const float* b3    = (const float*)d_in[12];
    float* out = (float*)d_out;
    (void)in_sizes; (void)n_in; (void)out_size;

    // Kernel 1: conv3x3 + relu -> g_y
    {
        dim3 grid(WWID / 64, HH / 4, BATCH * 2);
        conv3x3_relu_kernel<<<grid, 256>>>(x, w1, b1);
    }
    // Kernel 2: pooled -> reduce -> BN -> relu -> span -> g_wgt
    {
        dim3 grid((BATCH * OH * OW) / 256);
        genw_kernel<<<grid, 256>>>(wr, br, gamma, beta, mean, var, ws, bs);
    }
    // Kernel 3: involution + relu + 1x1 + relu -> out
    {
        dim3 grid((BATCH * OH * OW) / 256);
        inv_out_kernel<<<grid, 256>>>(w3, b3, out);
    }
}

// round 3
// speedup vs baseline: 2.7027x; 2.7027x over previous
#include <cuda_runtime.h>
#include <cstdint>

#define BATCH 4
#define CH    64
#define HH    512
#define WWID  512
#define OH    256
#define OW    256
#define REDC  16
#define NWGT  36

// conv tiling
#define NSTRIP 8          // 64-px wide strips
#define NHSEG  4          // 128-row segments
#define HSEG   128
#define NCHUNK 18         // 9 taps * 2 channel-halves (32ch)

// smem float offsets for conv kernel
#define SW_FLOATS  36864          // 18*4*8*32*2
#define SX_FLOATS  17952          // 4 * 66 * 68
#define OFF_SX     SW_FLOATS
#define OFF_BIAS   (SW_FLOATS + SX_FLOATS)
#define CONV_SMEM_BYTES ((OFF_BIAS + 64) * 4)   // 219,520

// Scratch
__device__ float g_y[(size_t)BATCH * CH * HH * WWID];
__device__ float g_xt[(size_t)BATCH * HH * WWID * CH];   // NHWC, tf32-rounded
__device__ float g_wt[SW_FLOATS];                         // fragment-packed weights
__device__ float g_wgt[(size_t)BATCH * NWGT * OH * OW];

// ---------------- helpers ----------------
__device__ __forceinline__ float tf32r(float v) {
    uint32_t t;
    asm("cvt.rna.tf32.f32 %0, %1;" : "=r"(t) : "f"(v));
    return __uint_as_float(t);
}
#define CP16(dst, src, sz) \
    asm volatile("cp.async.cg.shared.global [%0], [%1], 16, %2;" \
        :: "r"(dst), "l"(src), "r"(sz) : "memory")
#define CP_COMMIT() asm volatile("cp.async.commit_group;" ::: "memory")
#define CP_WAIT0()  asm volatile("cp.async.wait_group 0;" ::: "memory")

__device__ __forceinline__ void mma_tf32(float* d, const uint32_t* a,
                                         uint32_t b0, uint32_t b1) {
    asm volatile(
        "mma.sync.aligned.m16n8k8.row.col.f32.tf32.tf32.f32 "
        "{%0,%1,%2,%3},{%4,%5,%6,%7},{%8,%9},{%0,%1,%2,%3};"
        : "+f"(d[0]), "+f"(d[1]), "+f"(d[2]), "+f"(d[3])
        : "r"(a[0]), "r"(a[1]), "r"(a[2]), "r"(a[3]), "r"(b0), "r"(b1));
}

// ---------------------------------------------------------------------------
// Transpose x: NCHW -> NHWC (tf32 rounded)
// ---------------------------------------------------------------------------
__global__ __launch_bounds__(256) void transpose_kernel(const float* __restrict__ x)
{
    __shared__ float s[64][65];
    int tid = threadIdx.x;
    size_t P0 = (size_t)blockIdx.x * 64;
    int b = blockIdx.x >> 12;
    int ploc = (blockIdx.x & 4095) * 64;
#pragma unroll
    for (int i = 0; i < 16; i++) {
        int c = i * 4 + (tid >> 6);
        int p = tid & 63;
        s[p][c] = tf32r(x[((size_t)(b * 64 + c)) * (HH * WWID) + ploc + p]);
    }
    __syncthreads();
#pragma unroll
    for (int i = 0; i < 16; i++) {
        int p = i * 4 + (tid >> 6);
        int c = tid & 63;
        g_xt[(P0 + p) * 64 + c] = s[p][c];
    }
}

// ---------------------------------------------------------------------------
// Pack weights into per-lane mma-fragment order (tf32):
// idx = (((ch*4+kk)*8+ntg)*32 + lane)*2 + q
//  -> value B[k][oc]: oc = ntg*8 + lane>>2, ic = sec*32 + kk*8 + (lane&3) + 4q,
//     tap = ch>>1, sec = ch&1
// ---------------------------------------------------------------------------
__global__ __launch_bounds__(256) void wpack_kernel(const float* __restrict__ w1)
{
    int idx = blockIdx.x * 256 + threadIdx.x;
    if (idx >= SW_FLOATS) return;
    int q    = idx & 1;
    int lane = (idx >> 1) & 31;
    int ntg  = (idx >> 6) & 7;
    int kk   = (idx >> 9) & 3;
    int ch   = idx >> 11;
    int tap = ch >> 1, sec = ch & 1;
    int oc = ntg * 8 + (lane >> 2);
    int ic = sec * 32 + kk * 8 + (lane & 3) + 4 * q;
    g_wt[idx] = tf32r(w1[(oc * 64 + ic) * 9 + tap]);
}

// ---------------------------------------------------------------------------
// Conv3x3 + bias + relu via tf32 mma.sync, warp-specialized ring pipeline.
// 128 CTAs x 256 thr. warps 0-3: compute (m32 x n32), warps 4-7: producers.
// ---------------------------------------------------------------------------
__global__ __launch_bounds__(256, 1) void conv_mma_kernel(const float* __restrict__ b1)
{
    extern __shared__ float smem[];
    float* s_w = smem;
    float* s_x = smem + OFF_SX;
    float* s_bias = smem + OFF_BIAS;

    int tid = threadIdx.x;
    int warpid = tid >> 5;
    int lane = tid & 31;
    int qr = lane >> 2, qc = lane & 3;

    int bx = blockIdx.x;
    int hseg = bx & 3;
    int strip = (bx >> 2) & 7;
    int b = bx >> 5;
    int wbase = strip * 64;
    int h0 = hseg * HSEG;

    uint32_t sxb = (uint32_t)__cvta_generic_to_shared(s_x);
    uint32_t swb = (uint32_t)__cvta_generic_to_shared(s_w);

    // ---- prologue: stage weights (all threads) ----
    for (int i = tid; i < SW_FLOATS / 4; i += 256)
        CP16(swb + i * 16, g_wt + i * 4, 16);
    if (tid < 64) s_bias[tid] = b1[tid];

    // producer helper (lambda-style macro via function scope)
    int ptid = tid - 128;
    const size_t brow = (size_t)b * HH;

#define LOAD_ROW(AR, SLOT) do { \
    int _ar = (AR), _sl = (SLOT); \
    for (int i = ptid; i < 1056; i += 128) { \
        int px = i >> 4, c4 = i & 15; \
        int gw = wbase + px - 1; \
        int ok = ((unsigned)_ar < (unsigned)HH) && ((unsigned)gw < (unsigned)WWID); \
        const float* src = g_xt + ((brow + (ok ? _ar : 0)) * WWID + (ok ? gw : 0)) * 64 + c4 * 4; \
        CP16(sxb + (_sl * 4488 + px * 68 + c4 * 4) * 4, src, ok ? 16 : 0); \
    } } while (0)

    if (warpid >= 4) {
        LOAD_ROW(h0 - 1, (h0 - 1) & 3);
        LOAD_ROW(h0,     h0 & 3);
        LOAD_ROW(h0 + 1, (h0 + 1) & 3);
    }
    CP_COMMIT();
    CP_WAIT0();
    __syncthreads();

    // compute warp identity
    int wm = warpid & 1;        // m32 slot (px 0..31 / 32..63)
    int wn = warpid >> 1;       // n32 half (oc 0..31 / 32..63)
    int ms = wm * 32;
    int ocb = wn * 32;

    for (int hs = 0; hs < HSEG; hs++) {
        int h = h0 + hs;
        if (warpid >= 4) CP_WAIT0();
        __syncthreads();   // [A] row h+1 visible

        if (warpid < 4) {
            float acc[2][4][4];
#pragma unroll
            for (int f = 0; f < 2; f++)
#pragma unroll
                for (int nt = 0; nt < 4; nt++)
#pragma unroll
                    for (int j = 0; j < 4; j++) acc[f][nt][j] = 0.f;

#pragma unroll 1
            for (int ch = 0; ch < NCHUNK; ch++) {
                int tap = ch >> 1, sec = ch & 1;
                int kh = tap / 3, kw = tap - kh * 3;
                const float* xs = s_x + ((h + kh - 1) & 3) * 4488
                                  + (ms + kw) * 68 + sec * 32 + qc;
                const float* wp = s_w + ch * 2048 + (wn * 4) * 64 + lane * 2;
#pragma unroll
                for (int kk = 0; kk < 4; kk++) {
                    uint32_t a[2][4];
#pragma unroll
                    for (int f = 0; f < 2; f++) {
                        const float* ap = xs + kk * 8 + (f * 16 + qr) * 68;
                        a[f][0] = __float_as_uint(ap[0]);
                        a[f][1] = __float_as_uint(ap[544]);    // +8 rows
                        a[f][2] = __float_as_uint(ap[4]);      // k+4
                        a[f][3] = __float_as_uint(ap[548]);
                    }
                    const float* wk = wp + kk * 512;
#pragma unroll
                    for (int nt = 0; nt < 4; nt++) {
                        float2 bv = *(const float2*)(wk + nt * 64);
                        uint32_t b0 = __float_as_uint(bv.x);
                        uint32_t b1u = __float_as_uint(bv.y);
                        mma_tf32(acc[0][nt], a[0], b0, b1u);
                        mma_tf32(acc[1][nt], a[1], b0, b1u);
                    }
                }
            }

            // epilogue: bias + relu -> g_y (NCHW)
#pragma unroll
            for (int f = 0; f < 2; f++) {
                int px0 = wbase + ms + f * 16 + qr;
#pragma unroll
                for (int nt = 0; nt < 4; nt++) {
                    int oc0 = ocb + nt * 8 + qc * 2;
                    float bs0 = s_bias[oc0], bs1 = s_bias[oc0 + 1];
                    size_t p0 = ((size_t)(b * CH + oc0) * HH + h) * WWID + px0;
                    size_t p1 = ((size_t)(b * CH + oc0 + 1) * HH + h) * WWID + px0;
                    g_y[p0]     = fmaxf(acc[f][nt][0] + bs0, 0.f);
                    g_y[p1]     = fmaxf(acc[f][nt][1] + bs1, 0.f);
                    g_y[p0 + 8] = fmaxf(acc[f][nt][2] + bs0, 0.f);
                    g_y[p1 + 8] = fmaxf(acc[f][nt][3] + bs1, 0.f);
                }
            }
        } else {
            LOAD_ROW(h + 2, (h + 2) & 3);
            CP_COMMIT();
        }
        __syncthreads();   // [B]
    }
#undef LOAD_ROW
}

// ---------------------------------------------------------------------------
// Kernel-generating branch (fp32, unchanged)
// ---------------------------------------------------------------------------
__global__ __launch_bounds__(256) void genw_kernel(
    const float* __restrict__ wr, const float* __restrict__ br,
    const float* __restrict__ gamma, const float* __restrict__ beta,
    const float* __restrict__ mean,  const float* __restrict__ var,
    const float* __restrict__ ws,    const float* __restrict__ bs)
{
    __shared__ float s_wr[64][16];
    __shared__ float s_ws[36][16];
    __shared__ float s_scale[16], s_shift[16], s_br[16], s_bs[36];

    int tid = threadIdx.x;
    for (int i = tid; i < 1024; i += 256) {
        int r = i % 16, c = i / 16;
        s_wr[c][r] = wr[r * 64 + c];
    }
    for (int i = tid; i < 576; i += 256) {
        int r = i % 16, o = i / 16;
        s_ws[o][r] = ws[o * 16 + r];
    }
    if (tid < 16) {
        float sc = gamma[tid] * rsqrtf(var[tid] + 1e-5f);
        s_scale[tid] = sc;
        s_shift[tid] = beta[tid] - mean[tid] * sc;
        s_br[tid] = br[tid];
    }
    if (tid < 36) s_bs[tid] = bs[tid];
    __syncthreads();

    int idx = blockIdx.x * 256 + tid;
    int b = idx >> 16;
    int p = idx & 0xFFFF;
    int h = p >> 8;
    int w = p & 255;

    const float* yb = g_y + (size_t)b * CH * HH * WWID + (size_t)(2 * h) * WWID + 2 * w;

    float t[16];
#pragma unroll
    for (int r = 0; r < REDC; r++) t[r] = s_br[r];

    for (int c = 0; c < CH; c++) {
        const float* pp = yb + (size_t)c * HH * WWID;
        float pool = (pp[0] + pp[1] + pp[WWID] + pp[WWID + 1]) * 0.25f;
#pragma unroll
        for (int r = 0; r < REDC; r++) t[r] = fmaf(pool, s_wr[c][r], t[r]);
    }
#pragma unroll
    for (int r = 0; r < REDC; r++)
        t[r] = fmaxf(fmaf(t[r], s_scale[r], s_shift[r]), 0.f);

#pragma unroll 4
    for (int o = 0; o < NWGT; o++) {
        float a = s_bs[o];
#pragma unroll
        for (int r = 0; r < REDC; r++) a = fmaf(t[r], s_ws[o][r], a);
        g_wgt[(((size_t)b * NWGT + o) << 16) + p] = a;
    }
}

// ---------------------------------------------------------------------------
// Involution + relu + 1x1 + relu (fp32, unchanged)
// ---------------------------------------------------------------------------
__global__ __launch_bounds__(256) void inv_out_kernel(
    const float* __restrict__ w3, const float* __restrict__ b3,
    float* __restrict__ out)
{
    __shared__ float s_w3[64][64];
    __shared__ float s_b3[64];
    int tid = threadIdx.x;
    for (int i = tid; i < 4096; i += 256) s_w3[i >> 6][i & 63] = w3[i];
    if (tid < 64) s_b3[tid] = b3[tid];
    __syncthreads();

    int idx = blockIdx.x * 256 + tid;
    int b = idx >> 16;
    int p = idx & 0xFFFF;
    int h = p >> 8;
    int w = p & 255;

    const float* yb = g_y + (size_t)b * CH * HH * WWID;

    float z[64];
#pragma unroll
    for (int g = 0; g < 4; g++) {
        float wg[9];
#pragma unroll
        for (int k = 0; k < 9; k++)
            wg[k] = g_wgt[(((size_t)b * NWGT + g * 9 + k) << 16) + p];
#pragma unroll
        for (int cc = 0; cc < 16; cc++) {
            int c = g * 16 + cc;
            const float* yc = yb + (size_t)c * HH * WWID;
            float a = 0.f;
#pragma unroll
            for (int kh = 0; kh < 3; kh++) {
                int row = 2 * h - 1 + kh;
#pragma unroll
                for (int kw = 0; kw < 3; kw++) {
                    int col = 2 * w - 1 + kw;
                    float v = 0.f;
                    if ((unsigned)row < HH && (unsigned)col < WWID)
                        v = yc[(size_t)row * WWID + col];
                    a = fmaf(wg[kh * 3 + kw], v, a);
                }
            }
            z[c] = fmaxf(a, 0.f);
        }
    }

#pragma unroll 2
    for (int oc = 0; oc < CH; oc++) {
        float a = s_b3[oc];
#pragma unroll
        for (int c = 0; c < CH; c++) a = fmaf(z[c], s_w3[oc][c], a);
        out[(((size_t)b * CH + oc) << 16) + p] = fmaxf(a, 0.f);
    }
}

// ---------------------------------------------------------------------------
extern "C" void kernel_launch(void* const* d_in, const int* in_sizes, int n_in,
                              void* d_out, int out_size)
{
    const float* x     = (const float*)d_in[0];
    const float* w1    = (const float*)d_in[1];
    const float* b1    = (const float*)d_in[2];
    const float* wr    = (const float*)d_in[3];
    const float* br    = (const float*)d_in[4];
    const float* gamma = (const float*)d_in[5];
    const float* beta  = (const float*)d_in[6];
    const float* mean  = (const float*)d_in[7];
    const float* var   = (const float*)d_in[8];
    const float* ws    = (const float*)d_in[9];
    const float* bs    = (const float*)d_in[10];
    const float* w3    = (const float*)d_in[11];
    const float* b3    = (const float*)d_in[12];
    float* out = (float*)d_out;
    (void)in_sizes; (void)n_in; (void)out_size;

    cudaFuncSetAttribute(conv_mma_kernel,
                         cudaFuncAttributeMaxDynamicSharedMemorySize, CONV_SMEM_BYTES);

    transpose_kernel<<<16384, 256>>>(x);
    wpack_kernel<<<(SW_FLOATS + 255) / 256, 256>>>(w1);
    conv_mma_kernel<<<BATCH * NSTRIP * NHSEG, 256, CONV_SMEM_BYTES>>>(b1);
    genw_kernel<<<(BATCH * OH * OW) / 256, 256>>>(wr, br, gamma, beta, mean, var, ws, bs);
    inv_out_kernel<<<(BATCH * OH * OW) / 256, 256>>>(w3, b3, out);
}

// round 4
// speedup vs baseline: 3.9558x; 1.4636x over previous
#include <cuda_runtime.h>
#include <cuda_fp16.h>
#include <cstdint>

#define BATCH 4
#define CH    64
#define HH    512
#define WWID  512
#define OH    256
#define OW    256
#define REDC  16
#define NWGT  36

#define NSM      148
#define NROWU    16384          // 32 columns * 512 rows
#define SLOT_H   4752           // 66 px * 72 halves
#define SLOT_B   9504           // bytes per ring slot
#define NWU2     9216           // weight uint2 entries: 18*2*8*32

// conv smem byte offsets
#define OFF_W 0                 // uint2[9216] = 73728 B
#define OFF_X 73728             // 4 ring slots * 9504 = 38016 B
#define OFF_B 111744            // bias 64 floats
#define CONV_SMEM_BYTES 112000

// Scratch
__device__ float  g_y[(size_t)BATCH * CH * HH * WWID];                 // fp32 NCHW
__device__ __align__(16) __half g_xt[(size_t)BATCH * HH * WWID * CH];  // fp16 NHWC
__device__ __align__(16) uint2  g_wh[NWU2];                            // packed fp16 weights

// ---------------- helpers ----------------
#define CP16(dst, src, sz) \
    asm volatile("cp.async.cg.shared.global [%0], [%1], 16, %2;" \
        :: "r"(dst), "l"(src), "r"(sz) : "memory")
#define CP_COMMIT() asm volatile("cp.async.commit_group;" ::: "memory")
#define CP_WAIT0()  asm volatile("cp.async.wait_group 0;" ::: "memory")

__device__ __forceinline__ void mma_f16(float* d, const uint32_t* a,
                                        uint32_t b0, uint32_t b1) {
    asm volatile(
        "mma.sync.aligned.m16n8k16.row.col.f32.f16.f16.f32 "
        "{%0,%1,%2,%3},{%4,%5,%6,%7},{%8,%9},{%0,%1,%2,%3};"
        : "+f"(d[0]), "+f"(d[1]), "+f"(d[2]), "+f"(d[3])
        : "r"(a[0]), "r"(a[1]), "r"(a[2]), "r"(a[3]), "r"(b0), "r"(b1));
}

// ---------------------------------------------------------------------------
// Transpose x: NCHW fp32 -> NHWC fp16
// ---------------------------------------------------------------------------
__global__ __launch_bounds__(256) void transpose_kernel(const float* __restrict__ x)
{
    __shared__ float s[64][65];
    int tid = threadIdx.x;
    size_t P0 = (size_t)blockIdx.x * 64;
    int b = blockIdx.x >> 12;
    int ploc = (blockIdx.x & 4095) * 64;
#pragma unroll
    for (int i = 0; i < 16; i++) {
        int c = i * 4 + (tid >> 6);
        int p = tid & 63;
        s[p][c] = x[((size_t)(b * 64 + c)) * (HH * WWID) + ploc + p];
    }
    __syncthreads();
#pragma unroll
    for (int i = 0; i < 8; i++) {
        int p = i * 8 + (tid >> 5);
        int c0 = (tid & 31) * 2;
        *(__half2*)(g_xt + (P0 + p) * 64 + c0) = __floats2half2_rn(s[p][c0], s[p][c0 + 1]);
    }
}

// ---------------------------------------------------------------------------
// Pack weights into fp16 m16n8k16 B-fragment order.
// entry idx = ((ch*2+kk)*8+nt)*32 + lane, uint2 {b0,b1}
//  b0 = {w[oc][ic0], w[oc][ic0+1]},  b1 = {w[oc][ic0+8], w[oc][ic0+9]}
//  oc = nt*8 + (lane>>2), ic0 = sec*32 + kk*16 + 2*(lane&3), tap=ch>>1, sec=ch&1
// ---------------------------------------------------------------------------
__global__ __launch_bounds__(256) void wpack_kernel(const float* __restrict__ w1)
{
    int idx = blockIdx.x * 256 + threadIdx.x;
    if (idx >= NWU2) return;
    int lane = idx & 31;
    int nt   = (idx >> 5) & 7;
    int kk   = (idx >> 8) & 1;
    int ch   = idx >> 9;
    int tap = ch >> 1, sec = ch & 1;
    int oc = nt * 8 + (lane >> 2);
    int ic0 = sec * 32 + kk * 16 + 2 * (lane & 3);
    __half2 h0 = __floats2half2_rn(w1[(oc * 64 + ic0) * 9 + tap],
                                   w1[(oc * 64 + ic0 + 1) * 9 + tap]);
    __half2 h1 = __floats2half2_rn(w1[(oc * 64 + ic0 + 8) * 9 + tap],
                                   w1[(oc * 64 + ic0 + 9) * 9 + tap]);
    uint2 v;
    v.x = *(uint32_t*)&h0;
    v.y = *(uint32_t*)&h1;
    g_wh[idx] = v;
}

// ---------------------------------------------------------------------------
// Persistent fp16 mma.sync conv3x3 + bias + relu -> g_y (fp32 NCHW).
// 148 CTAs x 256 thr; warps 0-3 compute (m32 x n32), warps 4-7 producers.
// Work unit = one 64-px row of one (b,strip) column; CTA owns a contiguous range.
// ---------------------------------------------------------------------------
__global__ __launch_bounds__(256, 1) void conv_mma_kernel(const float* __restrict__ b1)
{
    extern __shared__ char smem[];
    uint2* s_w  = (uint2*)(smem + OFF_W);
    __half* s_x = (__half*)(smem + OFF_X);
    float* s_bias = (float*)(smem + OFF_B);

    int tid = threadIdx.x;
    int warpid = tid >> 5;
    int lane = tid & 31;
    int qr = lane >> 2, qc = lane & 3;
    int cta = blockIdx.x;

    uint32_t sb  = (uint32_t)__cvta_generic_to_shared(smem);
    uint32_t sxb = sb + OFF_X;

    // prologue: stage weights (all threads), bias
    for (int i = tid; i < NWU2 / 2; i += 256)
        CP16(sb + OFF_W + i * 16, (const char*)g_wh + i * 16, 16);
    if (tid < 64) s_bias[tid] = b1[tid];
    CP_COMMIT();
    CP_WAIT0();
    __syncthreads();

    int ptid = tid - 128;
    int s_idx = (int)((long long)cta * NROWU / NSM);
    int e_idx = (int)((long long)(cta + 1) * NROWU / NSM);

    int wm = warpid & 1, wn = warpid >> 1;
    int ms = wm * 32, ocb = wn * 32;

    int wbase = 0;
    size_t brow = 0;

#define LOAD_ROW(AR, SLOT) do { \
    int _ar = (AR), _sl = (SLOT); \
    for (int i = ptid; i < 528; i += 128) { \
        int px = i >> 3, c8 = i & 7; \
        int gw = wbase + px - 1; \
        int ok = ((unsigned)_ar < 512u) && ((unsigned)gw < 512u); \
        const __half* src = g_xt + (((brow + (ok ? _ar : 0)) << 9) + (ok ? gw : 0)) * 64 + c8 * 8; \
        CP16(sxb + _sl * SLOT_B + px * 144 + c8 * 16, src, ok ? 16 : 0); \
    } } while (0)

    int curcol = -1;
    for (int idx = s_idx; idx < e_idx; idx++) {
        int col = idx >> 9;
        int h = idx & 511;
        int b = col >> 3, strip = col & 7;
        wbase = strip * 64;
        brow = (size_t)b * 512;

        if (warpid >= 4) {
            if (col != curcol) {
                LOAD_ROW(h - 1, (h - 1) & 3);
                LOAD_ROW(h,     h & 3);
                LOAD_ROW(h + 1, (h + 1) & 3);
                CP_COMMIT();
            }
            CP_WAIT0();
        }
        curcol = col;
        __syncthreads();   // ring rows h-1..h+1 visible

        if (warpid < 4) {
            float acc[2][4][4];
#pragma unroll
            for (int f = 0; f < 2; f++)
#pragma unroll
                for (int nt = 0; nt < 4; nt++)
#pragma unroll
                    for (int j = 0; j < 4; j++) acc[f][nt][j] = 0.f;

#pragma unroll 1
            for (int ch = 0; ch < 18; ch++) {
                int tap = ch >> 1, sec = ch & 1;
                int kh = tap / 3, kw = tap - kh * 3;
                const __half* xs = s_x + ((h + kh - 1) & 3) * SLOT_H
                                 + (ms + kw) * 72 + sec * 32 + 2 * qc;
                const uint2* wp = s_w + (ch * 16 + wn * 4) * 32 + lane;
#pragma unroll
                for (int kk = 0; kk < 2; kk++) {
                    uint32_t a[2][4];
#pragma unroll
                    for (int f = 0; f < 2; f++) {
                        const __half* ap = xs + kk * 16 + (f * 16 + qr) * 72;
                        a[f][0] = *(const uint32_t*)(ap);
                        a[f][1] = *(const uint32_t*)(ap + 8 * 72);
                        a[f][2] = *(const uint32_t*)(ap + 8);
                        a[f][3] = *(const uint32_t*)(ap + 8 * 72 + 8);
                    }
                    const uint2* wk = wp + kk * 256;
#pragma unroll
                    for (int nt = 0; nt < 4; nt++) {
                        uint2 bv = wk[nt * 32];
                        mma_f16(acc[0][nt], a[0], bv.x, bv.y);
                        mma_f16(acc[1][nt], a[1], bv.x, bv.y);
                    }
                }
            }
            // epilogue: bias + relu -> g_y fp32 NCHW
#pragma unroll
            for (int f = 0; f < 2; f++) {
                int px0 = wbase + ms + f * 16 + qr;
#pragma unroll
                for (int nt = 0; nt < 4; nt++) {
                    int oc0 = ocb + nt * 8 + qc * 2;
                    float bs0 = s_bias[oc0], bs1 = s_bias[oc0 + 1];
                    size_t p0 = ((size_t)(b * CH + oc0) * HH + h) * WWID + px0;
                    size_t p1 = ((size_t)(b * CH + oc0 + 1) * HH + h) * WWID + px0;
                    g_y[p0]     = fmaxf(acc[f][nt][0] + bs0, 0.f);
                    g_y[p1]     = fmaxf(acc[f][nt][1] + bs1, 0.f);
                    g_y[p0 + 8] = fmaxf(acc[f][nt][2] + bs0, 0.f);
                    g_y[p1 + 8] = fmaxf(acc[f][nt][3] + bs1, 0.f);
                }
            }
        } else {
            LOAD_ROW(h + 2, (h + 2) & 3);
            CP_COMMIT();
        }
        __syncthreads();
    }
#undef LOAD_ROW
}

// ---------------------------------------------------------------------------
// Fused: avgpool -> 1x1(16)+BN+ReLU -> span(36)  ->  involution + ReLU
//        -> 1x1(64) + ReLU -> out.   One read of g_y, no g_wgt round-trip.
// 128 threads/block = 128 output pixels of one row.
// ---------------------------------------------------------------------------
__global__ __launch_bounds__(128) void fuse_kernel(
    const float* __restrict__ wr, const float* __restrict__ br,
    const float* __restrict__ gamma, const float* __restrict__ beta,
    const float* __restrict__ mean,  const float* __restrict__ var,
    const float* __restrict__ ws,    const float* __restrict__ bs,
    const float* __restrict__ w3,    const float* __restrict__ b3,
    float* __restrict__ out)
{
    __shared__ float s_wr[64][16];
    __shared__ float s_ws[36][16];
    __shared__ float s_w3[64][64];
    __shared__ float s_scale[16], s_shift[16], s_br[16], s_bs[36], s_b3[64];

    int tid = threadIdx.x;
    for (int i = tid; i < 1024; i += 128) {
        int r = i % 16, c = i / 16;
        s_wr[c][r] = wr[r * 64 + c];
    }
    for (int i = tid; i < 576; i += 128) {
        int r = i % 16, o = i / 16;
        s_ws[o][r] = ws[o * 16 + r];
    }
    for (int i = tid; i < 4096; i += 128) s_w3[i >> 6][i & 63] = w3[i];
    if (tid < 16) {
        float sc = gamma[tid] * rsqrtf(var[tid] + 1e-5f);
        s_scale[tid] = sc;
        s_shift[tid] = beta[tid] - mean[tid] * sc;
        s_br[tid] = br[tid];
    }
    if (tid < 36) s_bs[tid] = bs[tid];
    if (tid < 64) s_b3[tid] = b3[tid];
    __syncthreads();

    int idx = blockIdx.x * 128 + tid;
    int b = idx >> 16;
    int p = idx & 0xFFFF;
    int h = p >> 8;
    int w = p & 255;

    const float* yb = g_y + (size_t)b * CH * HH * WWID;

    // ---- pass 1: pooled -> t[16] ----
    const float* pp0 = yb + (size_t)(2 * h) * WWID + 2 * w;
    float t[16];
#pragma unroll
    for (int r = 0; r < REDC; r++) t[r] = s_br[r];
#pragma unroll 4
    for (int c = 0; c < CH; c++) {
        const float* pc = pp0 + (size_t)c * (HH * WWID);
        float2 u = *(const float2*)(pc);
        float2 v = *(const float2*)(pc + WWID);
        float pool = (u.x + u.y + v.x + v.y) * 0.25f;
#pragma unroll
        for (int r = 0; r < REDC; r++) t[r] = fmaf(pool, s_wr[c][r], t[r]);
    }
#pragma unroll
    for (int r = 0; r < REDC; r++)
        t[r] = fmaxf(fmaf(t[r], s_scale[r], s_shift[r]), 0.f);

    // ---- pass 2: per-group span weights + involution + relu ----
    float z[64];
#pragma unroll
    for (int g = 0; g < 4; g++) {
        float wg[9];
#pragma unroll
        for (int k = 0; k < 9; k++) {
            float a = s_bs[g * 9 + k];
#pragma unroll
            for (int r = 0; r < REDC; r++) a = fmaf(t[r], s_ws[g * 9 + k][r], a);
            wg[k] = a;
        }
#pragma unroll
        for (int cc = 0; cc < 16; cc++) {
            int c = g * 16 + cc;
            const float* yc = yb + (size_t)c * (HH * WWID);
            float a = 0.f;
#pragma unroll
            for (int kh = 0; kh < 3; kh++) {
                int row = 2 * h - 1 + kh;
#pragma unroll
                for (int kw = 0; kw < 3; kw++) {
                    int col = 2 * w - 1 + kw;
                    float v = 0.f;
                    if ((unsigned)row < (unsigned)HH && (unsigned)col < (unsigned)WWID)
                        v = yc[(size_t)row * WWID + col];
                    a = fmaf(wg[kh * 3 + kw], v, a);
                }
            }
            z[c] = fmaxf(a, 0.f);
        }
    }

    // ---- 1x1(64) + relu ----
#pragma unroll 2
    for (int oc = 0; oc < CH; oc++) {
        float a = s_b3[oc];
#pragma unroll
        for (int c = 0; c < CH; c++) a = fmaf(z[c], s_w3[oc][c], a);
        out[(((size_t)b * CH + oc) << 16) + p] = fmaxf(a, 0.f);
    }
}

// ---------------------------------------------------------------------------
extern "C" void kernel_launch(void* const* d_in, const int* in_sizes, int n_in,
                              void* d_out, int out_size)
{
    const float* x     = (const float*)d_in[0];
    const float* w1    = (const float*)d_in[1];
    const float* b1    = (const float*)d_in[2];
    const float* wr    = (const float*)d_in[3];
    const float* br    = (const float*)d_in[4];
    const float* gamma = (const float*)d_in[5];
    const float* beta  = (const float*)d_in[6];
    const float* mean  = (const float*)d_in[7];
    const float* var   = (const float*)d_in[8];
    const float* ws    = (const float*)d_in[9];
    const float* bs    = (const float*)d_in[10];
    const float* w3    = (const float*)d_in[11];
    const float* b3    = (const float*)d_in[12];
    float* out = (float*)d_out;
    (void)in_sizes; (void)n_in; (void)out_size;

    cudaFuncSetAttribute(conv_mma_kernel,
                         cudaFuncAttributeMaxDynamicSharedMemorySize, CONV_SMEM_BYTES);

    transpose_kernel<<<16384, 256>>>(x);
    wpack_kernel<<<(NWU2 + 255) / 256, 256>>>(w1);
    conv_mma_kernel<<<NSM, 256, CONV_SMEM_BYTES>>>(b1);
    fuse_kernel<<<(BATCH * OH * OW) / 128, 128>>>(wr, br, gamma, beta, mean, var,
                                                  ws, bs, w3, b3, out);
}

// round 5
// speedup vs baseline: 4.2885x; 1.0841x over previous
#include <cuda_runtime.h>
#include <cuda_fp16.h>
#include <cstdint>

#define BATCH 4
#define CH    64
#define HH    512
#define WWID  512
#define OH    256
#define OW    256
#define REDC  16
#define NWGT  36

#define NSM      148
#define NROWU    16384          // 32 columns * 512 rows
#define SLOT_H   4752           // 66 px * 72 halves
#define SLOT_B   9504           // bytes per ring slot
#define NWU2     9216           // conv weight uint2 entries: 18*2*8*32

// conv smem byte offsets
#define OFF_W 0                 // uint2[9216] = 73728 B
#define OFF_X 73728             // 4 ring slots * 9504 = 38016 B
#define OFF_B 111744            // bias 64 floats
#define CONV_SMEM_BYTES 112000

// Scratch
__device__ __align__(16) __half g_yh[(size_t)BATCH * HH * WWID * CH];  // y fp16 NHWC
__device__ __align__(16) __half g_xt[(size_t)BATCH * HH * WWID * CH];  // x fp16 NHWC
__device__ __align__(16) uint2  g_wh[NWU2];                            // conv weights (frag)
__device__ __align__(16) uint2  g_w3f[1024];                           // w3 frags [kk][nt][lane]

// ---------------- helpers ----------------
#define CP16(dst, src, sz) \
    asm volatile("cp.async.cg.shared.global [%0], [%1], 16, %2;" \
        :: "r"(dst), "l"(src), "r"(sz) : "memory")
#define CP_COMMIT() asm volatile("cp.async.commit_group;" ::: "memory")
#define CP_WAIT0()  asm volatile("cp.async.wait_group 0;" ::: "memory")

__device__ __forceinline__ void mma_f16(float* d, const uint32_t* a,
                                        uint32_t b0, uint32_t b1) {
    asm volatile(
        "mma.sync.aligned.m16n8k16.row.col.f32.f16.f16.f32 "
        "{%0,%1,%2,%3},{%4,%5,%6,%7},{%8,%9},{%0,%1,%2,%3};"
        : "+f"(d[0]), "+f"(d[1]), "+f"(d[2]), "+f"(d[3])
        : "r"(a[0]), "r"(a[1]), "r"(a[2]), "r"(a[3]), "r"(b0), "r"(b1));
}
#define LDMX4(r, addr) \
    asm volatile("ldmatrix.sync.aligned.m8n8.x4.shared.b16 {%0,%1,%2,%3}, [%4];" \
        : "=r"((r)[0]), "=r"((r)[1]), "=r"((r)[2]), "=r"((r)[3]) : "r"(addr))

// ---------------------------------------------------------------------------
// Transpose x: NCHW fp32 -> NHWC fp16
// ---------------------------------------------------------------------------
__global__ __launch_bounds__(256) void transpose_kernel(const float* __restrict__ x)
{
    __shared__ float s[64][65];
    int tid = threadIdx.x;
    size_t P0 = (size_t)blockIdx.x * 64;
    int b = blockIdx.x >> 12;
    int ploc = (blockIdx.x & 4095) * 64;
#pragma unroll
    for (int i = 0; i < 16; i++) {
        int c = i * 4 + (tid >> 6);
        int p = tid & 63;
        s[p][c] = x[((size_t)(b * 64 + c)) * (HH * WWID) + ploc + p];
    }
    __syncthreads();
#pragma unroll
    for (int i = 0; i < 8; i++) {
        int p = i * 8 + (tid >> 5);
        int c0 = (tid & 31) * 2;
        *(__half2*)(g_xt + (P0 + p) * 64 + c0) = __floats2half2_rn(s[p][c0], s[p][c0 + 1]);
    }
}

// ---------------------------------------------------------------------------
// Pack conv weights (fp16 m16n8k16 B-frag order) and w3 frags.
// ---------------------------------------------------------------------------
__global__ __launch_bounds__(256) void wpack_kernel(const float* __restrict__ w1,
                                                    const float* __restrict__ w3)
{
    int idx = blockIdx.x * 256 + threadIdx.x;
    if (idx < NWU2) {
        int lane = idx & 31;
        int nt   = (idx >> 5) & 7;
        int kk   = (idx >> 8) & 1;
        int ch   = idx >> 9;
        int tap = ch >> 1, sec = ch & 1;
        int oc = nt * 8 + (lane >> 2);
        int ic0 = sec * 32 + kk * 16 + 2 * (lane & 3);
        __half2 h0 = __floats2half2_rn(w1[(oc * 64 + ic0) * 9 + tap],
                                       w1[(oc * 64 + ic0 + 1) * 9 + tap]);
        __half2 h1 = __floats2half2_rn(w1[(oc * 64 + ic0 + 8) * 9 + tap],
                                       w1[(oc * 64 + ic0 + 9) * 9 + tap]);
        uint2 v;
        v.x = *(uint32_t*)&h0;
        v.y = *(uint32_t*)&h1;
        g_wh[idx] = v;
    }
    if (idx < 1024) {
        int lane = idx & 31;
        int nt   = (idx >> 5) & 7;
        int kk   = idx >> 8;
        int oc = nt * 8 + (lane >> 2);
        int c0 = kk * 16 + 2 * (lane & 3);
        __half2 h0 = __floats2half2_rn(w3[oc * 64 + c0],     w3[oc * 64 + c0 + 1]);
        __half2 h1 = __floats2half2_rn(w3[oc * 64 + c0 + 8], w3[oc * 64 + c0 + 9]);
        uint2 v;
        v.x = *(uint32_t*)&h0;
        v.y = *(uint32_t*)&h1;
        g_w3f[idx] = v;
    }
}

// ---------------------------------------------------------------------------
// Persistent fp16 mma conv3x3 + bias + relu -> g_yh (fp16 NHWC).
// 148 CTAs x 256 thr; warps 0-3 compute (m32 x n32), warps 4-7 producers.
// ---------------------------------------------------------------------------
__global__ __launch_bounds__(256, 1) void conv_mma_kernel(const float* __restrict__ b1)
{
    extern __shared__ char smem[];
    uint2* s_w  = (uint2*)(smem + OFF_W);
    __half* s_x = (__half*)(smem + OFF_X);
    float* s_bias = (float*)(smem + OFF_B);

    int tid = threadIdx.x;
    int warpid = tid >> 5;
    int lane = tid & 31;
    int qr = lane >> 2, qc = lane & 3;
    int cta = blockIdx.x;

    uint32_t sb  = (uint32_t)__cvta_generic_to_shared(smem);
    uint32_t sxb = sb + OFF_X;

    for (int i = tid; i < NWU2 / 2; i += 256)
        CP16(sb + OFF_W + i * 16, (const char*)g_wh + i * 16, 16);
    if (tid < 64) s_bias[tid] = b1[tid];
    CP_COMMIT();
    CP_WAIT0();
    __syncthreads();

    int ptid = tid - 128;
    int s_idx = (int)((long long)cta * NROWU / NSM);
    int e_idx = (int)((long long)(cta + 1) * NROWU / NSM);

    int wm = warpid & 1, wn = warpid >> 1;
    int ms = wm * 32, ocb = wn * 32;

    int wbase = 0;
    size_t brow = 0;

#define LOAD_ROW(AR, SLOT) do { \
    int _ar = (AR), _sl = (SLOT); \
    for (int i = ptid; i < 528; i += 128) { \
        int px = i >> 3, c8 = i & 7; \
        int gw = wbase + px - 1; \
        int ok = ((unsigned)_ar < 512u) && ((unsigned)gw < 512u); \
        const __half* src = g_xt + (((brow + (ok ? _ar : 0)) << 9) + (ok ? gw : 0)) * 64 + c8 * 8; \
        CP16(sxb + _sl * SLOT_B + px * 144 + c8 * 16, src, ok ? 16 : 0); \
    } } while (0)

    int curcol = -1;
    for (int idx = s_idx; idx < e_idx; idx++) {
        int col = idx >> 9;
        int h = idx & 511;
        int b = col >> 3, strip = col & 7;
        wbase = strip * 64;
        brow = (size_t)b * 512;

        if (warpid >= 4) {
            if (col != curcol) {
                LOAD_ROW(h - 1, (h - 1) & 3);
                LOAD_ROW(h,     h & 3);
                LOAD_ROW(h + 1, (h + 1) & 3);
                CP_COMMIT();
            }
            CP_WAIT0();
        }
        curcol = col;
        __syncthreads();

        if (warpid < 4) {
            float acc[2][4][4];
#pragma unroll
            for (int f = 0; f < 2; f++)
#pragma unroll
                for (int nt = 0; nt < 4; nt++)
#pragma unroll
                    for (int j = 0; j < 4; j++) acc[f][nt][j] = 0.f;

#pragma unroll 1
            for (int ch = 0; ch < 18; ch++) {
                int tap = ch >> 1, sec = ch & 1;
                int kh = tap / 3, kw = tap - kh * 3;
                const __half* xs = s_x + ((h + kh - 1) & 3) * SLOT_H
                                 + (ms + kw) * 72 + sec * 32 + 2 * qc;
                const uint2* wp = s_w + (ch * 16 + wn * 4) * 32 + lane;
#pragma unroll
                for (int kk = 0; kk < 2; kk++) {
                    uint32_t a[2][4];
#pragma unroll
                    for (int f = 0; f < 2; f++) {
                        const __half* ap = xs + kk * 16 + (f * 16 + qr) * 72;
                        a[f][0] = *(const uint32_t*)(ap);
                        a[f][1] = *(const uint32_t*)(ap + 8 * 72);
                        a[f][2] = *(const uint32_t*)(ap + 8);
                        a[f][3] = *(const uint32_t*)(ap + 8 * 72 + 8);
                    }
                    const uint2* wk = wp + kk * 256;
#pragma unroll
                    for (int nt = 0; nt < 4; nt++) {
                        uint2 bv = wk[nt * 32];
                        mma_f16(acc[0][nt], a[0], bv.x, bv.y);
                        mma_f16(acc[1][nt], a[1], bv.x, bv.y);
                    }
                }
            }
            // epilogue: bias + relu -> g_yh fp16 NHWC
            size_t rowoff = ((size_t)(b * 512 + h) << 9);
#pragma unroll
            for (int f = 0; f < 2; f++) {
                int px0 = wbase + ms + f * 16 + qr;
#pragma unroll
                for (int nt = 0; nt < 4; nt++) {
                    int oc0 = ocb + nt * 8 + qc * 2;
                    float bs0 = s_bias[oc0], bs1 = s_bias[oc0 + 1];
                    __half2 lo = __floats2half2_rn(fmaxf(acc[f][nt][0] + bs0, 0.f),
                                                   fmaxf(acc[f][nt][1] + bs1, 0.f));
                    __half2 hi = __floats2half2_rn(fmaxf(acc[f][nt][2] + bs0, 0.f),
                                                   fmaxf(acc[f][nt][3] + bs1, 0.f));
                    *(__half2*)(g_yh + ((rowoff + px0) << 6) + oc0) = lo;
                    *(__half2*)(g_yh + ((rowoff + px0 + 8) << 6) + oc0) = hi;
                }
            }
        } else {
            LOAD_ROW(h + 2, (h + 2) & 3);
            CP_COMMIT();
        }
        __syncthreads();
    }
#undef LOAD_ROW
}

// ---------------------------------------------------------------------------
// Fused: pool->1x1+BN+ReLU->span  -> involution+ReLU -> 1x1(mma)+ReLU -> out
// 128 threads = 128 pixels; y read as fp16 NHWC vectors; final 1x1 via mma.
// ---------------------------------------------------------------------------
__global__ __launch_bounds__(128) void fuse_kernel(
    const float* __restrict__ wr, const float* __restrict__ br,
    const float* __restrict__ gamma, const float* __restrict__ beta,
    const float* __restrict__ mean,  const float* __restrict__ var,
    const float* __restrict__ ws,    const float* __restrict__ bs,
    const float* __restrict__ b3,    float* __restrict__ out)
{
    __shared__ float s_wr[64][16];          // pre-scaled by 0.25
    __shared__ float s_ws[36][16];
    __shared__ uint2 s_w3f[4][8][32];
    __shared__ __align__(16) char s_buf[4][8320];   // per-warp: z (fp16) then out (fp32)
    __shared__ float s_scale[16], s_shift[16], s_br[16], s_bs[36], s_b3[64];

    int tid = threadIdx.x;
    int warp = tid >> 5, lane = tid & 31;
    int qr = lane >> 2, qc = lane & 3;

    for (int i = tid; i < 1024; i += 128) {
        int r = i % 16, c = i / 16;
        s_wr[c][r] = wr[r * 64 + c] * 0.25f;
    }
    for (int i = tid; i < 576; i += 128) {
        int r = i % 16, o = i / 16;
        s_ws[o][r] = ws[o * 16 + r];
    }
    for (int i = tid; i < 1024; i += 128) ((uint2*)s_w3f)[i] = g_w3f[i];
    if (tid < 16) {
        float sc = gamma[tid] * rsqrtf(var[tid] + 1e-5f);
        s_scale[tid] = sc;
        s_shift[tid] = beta[tid] - mean[tid] * sc;
        s_br[tid] = br[tid];
    }
    if (tid < 36) s_bs[tid] = bs[tid];
    if (tid < 64) s_b3[tid] = b3[tid];
    __syncthreads();

    int idx = blockIdx.x * 128 + tid;
    int b = idx >> 16;
    int p = idx & 0xFFFF;
    int h = p >> 8;
    int w = p & 255;

    const __half* Yb = g_yh + ((size_t)b << 24);   // 512*512*64 = 2^24

    // ---- phase A: pool (fp16 vec) -> t[16] ----
    float t[16];
#pragma unroll
    for (int r = 0; r < REDC; r++) t[r] = s_br[r];
    {
        const uint4* q0 = (const uint4*)(Yb + ((((size_t)(2 * h) << 9) + 2 * w) << 6));
        const uint4* q1 = (const uint4*)(Yb + ((((size_t)(2 * h + 1) << 9) + 2 * w) << 6));
#pragma unroll
        for (int i = 0; i < 8; i++) {
            uint4 va = q0[i], vb = q0[i + 8], vc = q1[i], vd = q1[i + 8];
            const __half2* ha = (const __half2*)&va;
            const __half2* hb = (const __half2*)&vb;
            const __half2* hc = (const __half2*)&vc;
            const __half2* hd = (const __half2*)&vd;
#pragma unroll
            for (int j = 0; j < 4; j++) {
                __half2 s = __hadd2(__hadd2(ha[j], hb[j]), __hadd2(hc[j], hd[j]));
                float2 f = __half22float2(s);
                int c0 = i * 8 + j * 2;
#pragma unroll
                for (int rq = 0; rq < 4; rq++) {
                    float4 w0 = *(const float4*)&s_wr[c0][rq * 4];
                    float4 w1 = *(const float4*)&s_wr[c0 + 1][rq * 4];
                    t[rq * 4 + 0] = fmaf(f.x, w0.x, fmaf(f.y, w1.x, t[rq * 4 + 0]));
                    t[rq * 4 + 1] = fmaf(f.x, w0.y, fmaf(f.y, w1.y, t[rq * 4 + 1]));
                    t[rq * 4 + 2] = fmaf(f.x, w0.z, fmaf(f.y, w1.z, t[rq * 4 + 2]));
                    t[rq * 4 + 3] = fmaf(f.x, w0.w, fmaf(f.y, w1.w, t[rq * 4 + 3]));
                }
            }
        }
    }
#pragma unroll
    for (int r = 0; r < REDC; r++)
        t[r] = fmaxf(fmaf(t[r], s_scale[r], s_shift[r]), 0.f);

    // ---- phase B: span weights + involution + relu -> z fp16 ----
    __half2 zh[32];
    int rm = 2 * h - 1;
#pragma unroll
    for (int g = 0; g < 4; g++) {
        float wg[9];
#pragma unroll
        for (int k = 0; k < 9; k++) {
            float a = s_bs[g * 9 + k];
#pragma unroll
            for (int rq = 0; rq < 4; rq++) {
                float4 wv = *(const float4*)&s_ws[g * 9 + k][rq * 4];
                a = fmaf(t[rq * 4 + 0], wv.x, fmaf(t[rq * 4 + 1], wv.y,
                    fmaf(t[rq * 4 + 2], wv.z, fmaf(t[rq * 4 + 3], wv.w, a))));
            }
            wg[k] = a;
        }
        float zf[16];
#pragma unroll
        for (int j = 0; j < 16; j++) zf[j] = 0.f;
#pragma unroll
        for (int kh = 0; kh < 3; kh++) {
            int row = rm + kh;
            bool rok = (row >= 0);
            const __half* rp = Yb + (((size_t)(rok ? row : 0)) << 15) + g * 16;
#pragma unroll
            for (int kw = 0; kw < 3; kw++) {
                int col = 2 * w - 1 + kw;
                bool ok = rok && (col >= 0);
                const uint4* pp = (const uint4*)(rp + ((size_t)(ok ? col : 0) << 6));
                uint4 v0 = ok ? pp[0] : make_uint4(0, 0, 0, 0);
                uint4 v1 = ok ? pp[1] : make_uint4(0, 0, 0, 0);
                float wk = wg[kh * 3 + kw];
                const __half2* h0 = (const __half2*)&v0;
                const __half2* h1 = (const __half2*)&v1;
#pragma unroll
                for (int j = 0; j < 4; j++) {
                    float2 f0 = __half22float2(h0[j]);
                    float2 f1 = __half22float2(h1[j]);
                    zf[j * 2 + 0] = fmaf(wk, f0.x, zf[j * 2 + 0]);
                    zf[j * 2 + 1] = fmaf(wk, f0.y, zf[j * 2 + 1]);
                    zf[8 + j * 2 + 0] = fmaf(wk, f1.x, zf[8 + j * 2 + 0]);
                    zf[8 + j * 2 + 1] = fmaf(wk, f1.y, zf[8 + j * 2 + 1]);
                }
            }
        }
#pragma unroll
        for (int m = 0; m < 8; m++)
            zh[g * 8 + m] = __floats2half2_rn(fmaxf(zf[2 * m], 0.f),
                                              fmaxf(zf[2 * m + 1], 0.f));
    }

    // ---- phase C: final 1x1 via mma ----
    char* bw = s_buf[warp];
    {
        uint4* zr = (uint4*)(bw + lane * 144);
#pragma unroll
        for (int i = 0; i < 8; i++) {
            uint4 v;
            v.x = *(uint32_t*)&zh[i * 4 + 0];
            v.y = *(uint32_t*)&zh[i * 4 + 1];
            v.z = *(uint32_t*)&zh[i * 4 + 2];
            v.w = *(uint32_t*)&zh[i * 4 + 3];
            zr[i] = v;
        }
    }
    __syncwarp();
    uint32_t a[2][4][4];
    {
        uint32_t sbase = (uint32_t)__cvta_generic_to_shared(bw);
        int rsel = lane & 15, ksel = lane >> 4;
#pragma unroll
        for (int m = 0; m < 2; m++)
#pragma unroll
            for (int kk = 0; kk < 4; kk++) {
                uint32_t addr = sbase + (m * 16 + rsel) * 144 + kk * 32 + ksel * 16;
                LDMX4(a[m][kk], addr);
            }
    }
    __syncwarp();
    float* so = (float*)bw;   // [32 px][65]
#pragma unroll
    for (int nt = 0; nt < 8; nt++) {
        float d0[4] = {0.f, 0.f, 0.f, 0.f}, d1[4] = {0.f, 0.f, 0.f, 0.f};
#pragma unroll
        for (int kk = 0; kk < 4; kk++) {
            uint2 bb = s_w3f[kk][nt][lane];
            mma_f16(d0, a[0][kk], bb.x, bb.y);
            mma_f16(d1, a[1][kk], bb.x, bb.y);
        }
        int oc0 = nt * 8 + qc * 2;
        so[qr * 65 + oc0]            = d0[0];
        so[qr * 65 + oc0 + 1]        = d0[1];
        so[(qr + 8) * 65 + oc0]      = d0[2];
        so[(qr + 8) * 65 + oc0 + 1]  = d0[3];
        so[(16 + qr) * 65 + oc0]     = d1[0];
        so[(16 + qr) * 65 + oc0 + 1] = d1[1];
        so[(24 + qr) * 65 + oc0]     = d1[2];
        so[(24 + qr) * 65 + oc0 + 1] = d1[3];
    }
    __syncwarp();
    int p0 = (blockIdx.x * 128 + warp * 32) & 0xFFFF;
#pragma unroll 8
    for (int oc = 0; oc < 64; oc++) {
        float v = so[lane * 65 + oc] + s_b3[oc];
        out[(((size_t)(b * 64 + oc)) << 16) + p0 + lane] = fmaxf(v, 0.f);
    }
}

// ---------------------------------------------------------------------------
extern "C" void kernel_launch(void* const* d_in, const int* in_sizes, int n_in,
                              void* d_out, int out_size)
{
    const float* x     = (const float*)d_in[0];
    const float* w1    = (const float*)d_in[1];
    const float* b1    = (const float*)d_in[2];
    const float* wr    = (const float*)d_in[3];
    const float* br    = (const float*)d_in[4];
    const float* gamma = (const float*)d_in[5];
    const float* beta  = (const float*)d_in[6];
    const float* mean  = (const float*)d_in[7];
    const float* var   = (const float*)d_in[8];
    const float* ws    = (const float*)d_in[9];
    const float* bs    = (const float*)d_in[10];
    const float* w3    = (const float*)d_in[11];
    const float* b3    = (const float*)d_in[12];
    float* out = (float*)d_out;
    (void)in_sizes; (void)n_in; (void)out_size;

    cudaFuncSetAttribute(conv_mma_kernel,
                         cudaFuncAttributeMaxDynamicSharedMemorySize, CONV_SMEM_BYTES);

    transpose_kernel<<<16384, 256>>>(x);
    wpack_kernel<<<(NWU2 + 255) / 256, 256>>>(w1, w3);
    conv_mma_kernel<<<NSM, 256, CONV_SMEM_BYTES>>>(b1);
    fuse_kernel<<<(BATCH * OH * OW) / 128, 128>>>(wr, br, gamma, beta, mean, var,
                                                  ws, bs, b3, out);
}